// round 4
// baseline (speedup 1.0000x reference)
#include <cuda_runtime.h>
#include <cstdint>

// Problem constants
#define NN 50000
#define EE 1600000
#define ET (EE + NN)
#define DHD 128
#define PERM_SZ (NN + 3 * 128)
#define GEMM_BLKS ((NN + 127) / 128)       // 391
#define SELF_BLKS ((PERM_SZ + 127) / 128)  // 396

// Dynamic smem (floats): Ahi[128][68] | Alo[128][68] | Bfrag chunk [8][16][64]
#define SA_STRIDE 68
#define OFF_AHI 0
#define OFF_ALO (128 * SA_STRIDE)
#define OFF_B (2 * 128 * SA_STRIDE)
#define GEMM_SMEM ((2 * 128 * SA_STRIDE + 8 * 16 * 64) * 4)  // 102400 B

// ---------------- device scratch ----------------
__device__ float g_y[(size_t)NN * DHD];
__device__ float g_bufA[(size_t)NN * DHD];
__device__ float g_bufB[(size_t)NN * DHD];
__device__ float g_z[(size_t)NN * DHD];
__device__ float g_rh[(size_t)NN * DHD];
__device__ float g_WS[18 * DHD * DHD];      // per-conv per-role W@S (plain [k][n])
__device__ uint32_t g_Bimg[24 * DHD * DHD]; // tf32 fragment-ordered B images
__device__ int g_deg[NN];
__device__ int g_off[NN + 1];
__device__ int g_pos[NN];
__device__ int g_csr[ET];
__device__ int g_roleCnt[3];
__device__ int g_rolePadOff[4];
__device__ int g_rolePos[3];
__device__ int g_perm[PERM_SZ];

// ---------------- tf32 helpers ----------------
__device__ __forceinline__ uint32_t f2tf32(float x) {
    uint32_t r;
    asm("cvt.rna.tf32.f32 %0, %1;" : "=r"(r) : "f"(x));
    return r;
}
__device__ __forceinline__ void split_tf32(float x, uint32_t& hi, uint32_t& lo) {
    asm("cvt.rna.tf32.f32 %0, %1;" : "=r"(hi) : "f"(x));
    float r = x - __uint_as_float(hi);
    asm("cvt.rna.tf32.f32 %0, %1;" : "=r"(lo) : "f"(r));
}
__device__ __forceinline__ void mma8(float* c, const uint32_t* a, uint2 b) {
    asm volatile(
        "mma.sync.aligned.m16n8k8.row.col.f32.tf32.tf32.f32 "
        "{%0,%1,%2,%3},{%4,%5,%6,%7},{%8,%9},{%0,%1,%2,%3};"
        : "+f"(c[0]), "+f"(c[1]), "+f"(c[2]), "+f"(c[3])
        : "r"(a[0]), "r"(a[1]), "r"(a[2]), "r"(a[3]), "r"(b.x), "r"(b.y));
}

// ---------------- preprocessing ----------------
__global__ void init_kernel() {
    int i = blockIdx.x * blockDim.x + threadIdx.x;
    if (i < NN) g_deg[i] = 0;
    if (i < 3) g_roleCnt[i] = 0;
    if (i < PERM_SZ) g_perm[i] = -1;
}

__global__ void count_kernel(const int* __restrict__ ei, const int* __restrict__ role) {
    int e = blockIdx.x * blockDim.x + threadIdx.x;
    if (e < ET) {
        int c = (e < EE) ? ei[EE + e] : (e - EE);
        atomicAdd(&g_deg[c], 1);
    }
    if (e < NN) atomicAdd(&g_roleCnt[role[e]], 1);
}

__global__ void scan_kernel() {
    __shared__ int warpsum[32];
    __shared__ int s_tot;
    __shared__ int s_carry;
    int t = threadIdx.x, lane = t & 31, w = t >> 5;
    if (t == 0) s_carry = 0;
    __syncthreads();
    for (int base = 0; base < NN; base += 1024) {
        int v = (base + t < NN) ? g_deg[base + t] : 0;
        int s = v;
#pragma unroll
        for (int o = 1; o < 32; o <<= 1) {
            int n = __shfl_up_sync(~0u, s, o);
            if (lane >= o) s += n;
        }
        if (lane == 31) warpsum[w] = s;
        __syncthreads();
        if (w == 0) {
            int ws = warpsum[lane];
            int t2 = ws;
#pragma unroll
            for (int o = 1; o < 32; o <<= 1) {
                int n = __shfl_up_sync(~0u, t2, o);
                if (lane >= o) t2 += n;
            }
            warpsum[lane] = t2 - ws;
            if (lane == 31) s_tot = t2;
        }
        __syncthreads();
        int excl = s_carry + warpsum[w] + s - v;
        if (base + t < NN) {
            g_off[base + t] = excl;
            g_pos[base + t] = excl;
        }
        __syncthreads();
        if (t == 0) s_carry += s_tot;
        __syncthreads();
    }
    if (t == 0) {
        g_off[NN] = s_carry;
        int o = 0;
        for (int r2 = 0; r2 < 3; r2++) {
            g_rolePadOff[r2] = o;
            g_rolePos[r2] = o;
            o += ((g_roleCnt[r2] + 127) >> 7) << 7;
        }
        g_rolePadOff[3] = o;
    }
}

__global__ void fill_kernel(const int* __restrict__ ei, const int* __restrict__ role) {
    int e = blockIdx.x * blockDim.x + threadIdx.x;
    if (e < ET) {
        int r, c;
        if (e < EE) { r = ei[e]; c = ei[EE + e]; }
        else { r = e - EE; c = e - EE; }
        int p = atomicAdd(&g_pos[c], 1);
        g_csr[p] = r;
    }
    if (e < NN) {
        int q = atomicAdd(&g_rolePos[role[e]], 1);
        g_perm[q] = e;
    }
}

// ---------------- WS[conv][r] = W @ S[r] (fp32 exact, tiny) ----------------
__global__ void __launch_bounds__(256) ws_all_kernel(
    const float* W0, const float* S0, const float* W1, const float* S1,
    const float* W2, const float* S2, const float* W3, const float* S3,
    const float* W4, const float* S4, const float* W5, const float* S5) {
    int conv = blockIdx.z, r = blockIdx.y, ct = blockIdx.x;
    const float* W;
    const float* S;
    switch (conv) {
        case 0: W = W0; S = S0; break;
        case 1: W = W1; S = S1; break;
        case 2: W = W2; S = S2; break;
        case 3: W = W3; S = S3; break;
        case 4: W = W4; S = S4; break;
        default: W = W5; S = S5; break;
    }
    const float* B = S + ((size_t)r << 14) + ct * 32;
    float* C = g_WS + (((size_t)conv * 3 + r) << 14) + ct * 32;

    __shared__ float As[DHD][33];
    __shared__ float Bs[32][33];
    int tid = threadIdx.x;
    int tr = tid >> 4, tc = tid & 15;
    float acc[8][2] = {};
    for (int kc = 0; kc < DHD; kc += 32) {
#pragma unroll
        for (int t = 0; t < 4; t++) {
            int idx = tid + t * 256;
            int row = idx >> 3;
            int kq = (idx & 7) << 2;
            float4 v = *(const float4*)&W[(size_t)row * DHD + kc + kq];
            As[row][kq] = v.x; As[row][kq + 1] = v.y; As[row][kq + 2] = v.z; As[row][kq + 3] = v.w;
        }
#pragma unroll
        for (int t = 0; t < 4; t++) {
            int idx = tid + t * 256;
            int kk = idx >> 5;
            int j = idx & 31;
            Bs[kk][j] = B[(size_t)(kc + kk) * DHD + j];
        }
        __syncthreads();
#pragma unroll 8
        for (int kk = 0; kk < 32; kk++) {
            float b0 = Bs[kk][tc * 2], b1 = Bs[kk][tc * 2 + 1];
#pragma unroll
            for (int i = 0; i < 8; i++) {
                float a = As[tr * 8 + i][kk];
                acc[i][0] += a * b0;
                acc[i][1] += a * b1;
            }
        }
        __syncthreads();
    }
#pragma unroll
    for (int i = 0; i < 8; i++) {
        C[(size_t)(tr * 8 + i) * DHD + tc * 2] = acc[i][0];
        C[(size_t)(tr * 8 + i) * DHD + tc * 2 + 1] = acc[i][1];
    }
}

// ---------------- build tf32 fragment-ordered B images ----------------
// Layout: img[kit(16)][nt(16)][lane*2+half], value = B[k=kit*8+lane%4+half*4][n=nt*8+lane/4]
__global__ void __launch_bounds__(256) img_kernel(const float* W0, const float* W1,
                                                  const float* W2, const float* W3,
                                                  const float* W4, const float* W5) {
    int m = blockIdx.x;
    const float* src;
    switch (m) {
        case 0: src = W0; break;
        case 1: src = W1; break;
        case 2: src = W2; break;
        case 3: src = W3; break;
        case 4: src = W4; break;
        case 5: src = W5; break;
        default: src = g_WS + (size_t)(m - 6) * 16384; break;
    }
    uint32_t* dst = g_Bimg + (size_t)m * 16384;
    for (int i = threadIdx.x; i < 16384; i += 256) {
        int l2 = i & 63;
        int nt = (i >> 6) & 15;
        int kit = i >> 10;
        int lane = l2 >> 1, half = l2 & 1;
        int k = kit * 8 + (lane & 3) + half * 4;
        int n = nt * 8 + (lane >> 2);
        dst[i] = f2tf32(src[k * DHD + n]);
    }
}

// ---------------- tf32 tensor-core GEMM mainloop (shared by both kernels) --------
// acc[mt 2][nt 8][4]; returns with accumulators filled. rowsrc(row)->global row or -1.
__device__ __forceinline__ void gemm_mainloop(float (*acc)[8][4], uint32_t* sm,
                                              const float* __restrict__ Xp,
                                              const int* rows, int matIdx, int tid) {
    int lane = tid & 31, wid = tid >> 5;
    int warp_m = wid & 3, warp_n = wid >> 2;
    uint32_t* sAhi = sm + OFF_AHI;
    uint32_t* sAlo = sm + OFF_ALO;
    uint32_t* sB = sm + OFF_B;

    for (int kc = 0; kc < 2; kc++) {
        if (kc) __syncthreads();
        // A chunk: 128 rows x 64 k, split hi/lo
#pragma unroll
        for (int it = 0; it < 8; it++) {
            int i = tid + it * 256;  // 0..2047 float4 slots
            int row = i >> 4, f4 = i & 15;
            int gr = rows[row];
            float4 v = make_float4(0.f, 0.f, 0.f, 0.f);
            if (gr >= 0) v = *(const float4*)(Xp + (size_t)gr * DHD + kc * 64 + f4 * 4);
            int base = row * SA_STRIDE + f4 * 4;
            uint32_t h0, l0, h1, l1, h2, l2, h3, l3;
            split_tf32(v.x, h0, l0);
            split_tf32(v.y, h1, l1);
            split_tf32(v.z, h2, l2);
            split_tf32(v.w, h3, l3);
            *(uint4*)(sAhi + base) = make_uint4(h0, h1, h2, h3);
            *(uint4*)(sAlo + base) = make_uint4(l0, l1, l2, l3);
        }
        // B chunk: already fragment-ordered tf32
        const uint4* bsrc = (const uint4*)(g_Bimg + (size_t)matIdx * 16384 + kc * 8192);
#pragma unroll
        for (int it = 0; it < 8; it++) {
            ((uint4*)sB)[tid + it * 256] = bsrc[tid + it * 256];
        }
        __syncthreads();

#pragma unroll
        for (int kit = 0; kit < 8; kit++) {
            uint32_t ah[2][4], al[2][4];
#pragma unroll
            for (int mt = 0; mt < 2; mt++) {
                int r0 = warp_m * 32 + mt * 16 + (lane >> 2);
                int kk = kit * 8 + (lane & 3);
                ah[mt][0] = sAhi[r0 * SA_STRIDE + kk];
                ah[mt][1] = sAhi[(r0 + 8) * SA_STRIDE + kk];
                ah[mt][2] = sAhi[r0 * SA_STRIDE + kk + 4];
                ah[mt][3] = sAhi[(r0 + 8) * SA_STRIDE + kk + 4];
                al[mt][0] = sAlo[r0 * SA_STRIDE + kk];
                al[mt][1] = sAlo[(r0 + 8) * SA_STRIDE + kk];
                al[mt][2] = sAlo[r0 * SA_STRIDE + kk + 4];
                al[mt][3] = sAlo[(r0 + 8) * SA_STRIDE + kk + 4];
            }
#pragma unroll
            for (int nt = 0; nt < 8; nt++) {
                int gnt = warp_n * 8 + nt;
                uint2 b = *(uint2*)(sB + (kit * 16 + gnt) * 64 + lane * 2);
#pragma unroll
                for (int mt = 0; mt < 2; mt++) {
                    mma8(acc[mt][nt], ah[mt], b);
                    mma8(acc[mt][nt], al[mt], b);
                }
            }
        }
    }
}

// ---------------- GEMM: Y = gate(X @ W) + b ----------------
__global__ void __launch_bounds__(256) gemm_y_tc(const float* __restrict__ X, int matIdx,
                                                 const float* __restrict__ Wg,
                                                 const float* __restrict__ bg,
                                                 const float* __restrict__ bvec,
                                                 const int* __restrict__ role) {
    extern __shared__ __align__(16) uint32_t sm[];
    __shared__ float sg[3][DHD];
    __shared__ float bb[3][DHD];
    __shared__ int role_s[DHD];
    __shared__ int rows[DHD];

    int tid = threadIdx.x;
    int r0 = blockIdx.x * DHD;
    const float* Xp = X ? X : g_rh;

    for (int t = tid; t < 3 * DHD; t += 256) {
        int r = t >> 7, c = t & 127;
        float wv = Wg[t] + bg[t];
        sg[r][c] = 1.0f / (1.0f + __expf(-wv));
        bb[r][c] = bvec ? bvec[t] : 0.0f;
    }
    if (tid < DHD) {
        int gr = r0 + tid;
        rows[tid] = (gr < NN) ? gr : -1;
        role_s[tid] = (gr < NN) ? role[gr] : 0;
    }
    __syncthreads();

    float acc[2][8][4];
#pragma unroll
    for (int a = 0; a < 2; a++)
#pragma unroll
        for (int b = 0; b < 8; b++)
#pragma unroll
            for (int c = 0; c < 4; c++) acc[a][b][c] = 0.f;

    gemm_mainloop(acc, sm, Xp, rows, matIdx, tid);

    int lane = tid & 31, wid = tid >> 5;
    int warp_m = wid & 3, warp_n = wid >> 2;
#pragma unroll
    for (int mt = 0; mt < 2; mt++) {
#pragma unroll
        for (int h = 0; h < 2; h++) {
            int lrow = warp_m * 32 + mt * 16 + (lane >> 2) + h * 8;
            int grow = r0 + lrow;
            if (grow >= NN) continue;
            int rl = role_s[lrow];
            float* yp = g_y + (size_t)grow * DHD;
#pragma unroll
            for (int nt = 0; nt < 8; nt++) {
                int col = warp_n * 64 + nt * 8 + (lane & 3) * 2;
                float v0 = acc[mt][nt][h * 2], v1 = acc[mt][nt][h * 2 + 1];
                float2 o;
                o.x = v0 * sg[rl][col] + bb[rl][col];
                o.y = v1 * sg[rl][col + 1] + bb[rl][col + 1];
                *(float2*)(yp + col) = o;
            }
        }
    }
}

// ---------------- GEMM: C[node] += X[node] @ WS[conv][role] ----------------
__global__ void __launch_bounds__(256) gemm_self_tc(const float* __restrict__ X, int convIdx,
                                                    int sel) {
    int rowBase = blockIdx.x * DHD;
    if (rowBase >= g_rolePadOff[3]) return;
    extern __shared__ __align__(16) uint32_t sm[];
    __shared__ int rows[DHD];

    float* C = sel ? g_bufB : g_bufA;
    const float* Xp = X ? X : g_rh;
    int tid = threadIdx.x;

    int r = 0;
    if (rowBase >= g_rolePadOff[1]) r = 1;
    if (rowBase >= g_rolePadOff[2]) r = 2;
    int matIdx = 6 + convIdx * 3 + r;

    if (tid < DHD) rows[tid] = (rowBase + tid < PERM_SZ) ? g_perm[rowBase + tid] : -1;
    __syncthreads();

    float acc[2][8][4];
#pragma unroll
    for (int a = 0; a < 2; a++)
#pragma unroll
        for (int b = 0; b < 8; b++)
#pragma unroll
            for (int c = 0; c < 4; c++) acc[a][b][c] = 0.f;

    gemm_mainloop(acc, sm, Xp, rows, matIdx, tid);

    int lane = tid & 31, wid = tid >> 5;
    int warp_m = wid & 3, warp_n = wid >> 2;
#pragma unroll
    for (int mt = 0; mt < 2; mt++) {
#pragma unroll
        for (int h = 0; h < 2; h++) {
            int lrow = warp_m * 32 + mt * 16 + (lane >> 2) + h * 8;
            int node = rows[lrow];
            if (node < 0) continue;
            float* cp = C + (size_t)node * DHD;
#pragma unroll
            for (int nt = 0; nt < 8; nt++) {
                int col = warp_n * 64 + nt * 8 + (lane & 3) * 2;
                float2 o = *(float2*)(cp + col);
                o.x += acc[mt][nt][h * 2];
                o.y += acc[mt][nt][h * 2 + 1];
                *(float2*)(cp + col) = o;
            }
        }
    }
}

// ---------------- SpMM: C[i] = mean of Y[src] over incoming edges ----------------
__global__ void __launch_bounds__(256) spmm_kernel(int sel) {
    float* C = sel ? g_bufB : g_bufA;
    int w = (blockIdx.x * blockDim.x + threadIdx.x) >> 5;
    int lane = threadIdx.x & 31;
    if (w >= NN) return;
    int s = g_off[w], e = g_off[w + 1];
    float4 a0 = make_float4(0.f, 0.f, 0.f, 0.f);
    float4 a1 = make_float4(0.f, 0.f, 0.f, 0.f);
    int p = s;
    for (; p + 2 <= e; p += 2) {
        int s0 = g_csr[p], s1 = g_csr[p + 1];
        float4 v0 = *(const float4*)(g_y + (size_t)s0 * DHD + (lane << 2));
        float4 v1 = *(const float4*)(g_y + (size_t)s1 * DHD + (lane << 2));
        a0.x += v0.x; a0.y += v0.y; a0.z += v0.z; a0.w += v0.w;
        a1.x += v1.x; a1.y += v1.y; a1.z += v1.z; a1.w += v1.w;
    }
    if (p < e) {
        int s0 = g_csr[p];
        float4 v0 = *(const float4*)(g_y + (size_t)s0 * DHD + (lane << 2));
        a0.x += v0.x; a0.y += v0.y; a0.z += v0.z; a0.w += v0.w;
    }
    float inv = 1.0f / (float)(e - s);
    float4 r;
    r.x = (a0.x + a1.x) * inv;
    r.y = (a0.y + a1.y) * inv;
    r.z = (a0.z + a1.z) * inv;
    r.w = (a0.w + a1.w) * inv;
    *(float4*)(C + (size_t)w * DHD + (lane << 2)) = r;
}

// ---------------- elementwise combines ----------------
__device__ __forceinline__ float sigm(float x) { return 1.0f / (1.0f + __expf(-x)); }

__global__ void combine_zr_kernel(const float* __restrict__ h, int mode) {
    size_t i = (size_t)blockIdx.x * blockDim.x + threadIdx.x;
    if (i >= (size_t)NN * 32) return;
    float4 a = ((const float4*)g_bufA)[i];
    float4 b = ((const float4*)g_bufB)[i];
    float4 o;
    o.x = sigm(fmaxf(a.x, 0.f) + fmaxf(b.x, 0.f));
    o.y = sigm(fmaxf(a.y, 0.f) + fmaxf(b.y, 0.f));
    o.z = sigm(fmaxf(a.z, 0.f) + fmaxf(b.z, 0.f));
    o.w = sigm(fmaxf(a.w, 0.f) + fmaxf(b.w, 0.f));
    if (mode) {
        float4 hv = ((const float4*)h)[i];
        o.x *= hv.x; o.y *= hv.y; o.z *= hv.z; o.w *= hv.w;
        ((float4*)g_rh)[i] = o;
    } else {
        ((float4*)g_z)[i] = o;
    }
}

__global__ void combine_h_kernel(const float* __restrict__ h, float* __restrict__ out) {
    size_t i = (size_t)blockIdx.x * blockDim.x + threadIdx.x;
    if (i >= (size_t)NN * 32) return;
    float4 a = ((const float4*)g_bufA)[i];
    float4 b = ((const float4*)g_bufB)[i];
    float4 zv = ((const float4*)g_z)[i];
    float4 hv = ((const float4*)h)[i];
    float4 o;
    float ht;
    ht = tanhf(fmaxf(a.x, 0.f) + fmaxf(b.x, 0.f));
    o.x = zv.x * hv.x + (1.0f - zv.x) * ht;
    ht = tanhf(fmaxf(a.y, 0.f) + fmaxf(b.y, 0.f));
    o.y = zv.y * hv.y + (1.0f - zv.y) * ht;
    ht = tanhf(fmaxf(a.z, 0.f) + fmaxf(b.z, 0.f));
    o.z = zv.z * hv.z + (1.0f - zv.z) * ht;
    ht = tanhf(fmaxf(a.w, 0.f) + fmaxf(b.w, 0.f));
    o.w = zv.w * hv.w + (1.0f - zv.w) * ht;
    ((float4*)out)[i] = o;
}

// ---------------- host launch ----------------
struct CW {
    const float *W, *Wg, *bg, *S, *b;
};

static void run_conv(const float* X, const CW& w, int convIdx, int sel, const int* role) {
    gemm_y_tc<<<GEMM_BLKS, 256, GEMM_SMEM>>>(X, convIdx, w.Wg, w.bg, w.b, role);
    spmm_kernel<<<(NN * 32 + 255) / 256, 256>>>(sel);
    gemm_self_tc<<<SELF_BLKS, 256, GEMM_SMEM>>>(X, convIdx, sel);
}

extern "C" void kernel_launch(void* const* d_in, const int* in_sizes, int n_in,
                              void* d_out, int out_size) {
    cudaFuncSetAttribute(gemm_y_tc, cudaFuncAttributeMaxDynamicSharedMemorySize, GEMM_SMEM);
    cudaFuncSetAttribute(gemm_self_tc, cudaFuncAttributeMaxDynamicSharedMemorySize, GEMM_SMEM);

    int iEdge = 2, iH = 1;
    if (in_sizes[1] == 2 * EE) { iEdge = 1; iH = 2; }
    const float* x = (const float*)d_in[0];
    const float* h_prev = (const float*)d_in[iH];
    const int* ei = (const int*)d_in[iEdge];
    const int* role = (const int*)d_in[3];

    const float* P[27];
    for (int i = 0; i < 27 && (4 + i) < n_in; i++) P[i] = (const float*)d_in[4 + i];
    CW xz{P[0], P[1], P[2], P[3], P[4]};
    CW hz{P[5], P[6], P[7], P[8], nullptr};
    CW xr{P[9], P[10], P[11], P[12], P[13]};
    CW hr{P[14], P[15], P[16], P[17], nullptr};
    CW xh{P[18], P[19], P[20], P[21], P[22]};
    CW hh{P[23], P[24], P[25], P[26], nullptr};
    float* out = (float*)d_out;

    init_kernel<<<(PERM_SZ + 255) / 256, 256>>>();
    count_kernel<<<(ET + 255) / 256, 256>>>(ei, role);
    scan_kernel<<<1, 1024>>>();
    fill_kernel<<<(ET + 255) / 256, 256>>>(ei, role);
    ws_all_kernel<<<dim3(4, 3, 6), 256>>>(xz.W, xz.S, hz.W, hz.S, xr.W, xr.S,
                                          hr.W, hr.S, xh.W, xh.S, hh.W, hh.S);
    img_kernel<<<24, 256>>>(xz.W, hz.W, xr.W, hr.W, xh.W, hh.W);

    // z gate
    run_conv(x, xz, 0, 0, role);
    run_conv(h_prev, hz, 1, 1, role);
    combine_zr_kernel<<<(NN * 32 + 255) / 256, 256>>>(h_prev, 0);
    // r gate -> r * h_prev
    run_conv(x, xr, 2, 0, role);
    run_conv(h_prev, hr, 3, 1, role);
    combine_zr_kernel<<<(NN * 32 + 255) / 256, 256>>>(h_prev, 1);
    // h_tilde + final GRU mix
    run_conv(x, xh, 4, 0, role);
    run_conv(nullptr, hh, 5, 1, role);
    combine_h_kernel<<<(NN * 32 + 255) / 256, 256>>>(h_prev, out);
}